// round 14
// baseline (speedup 1.0000x reference)
#include <cuda_runtime.h>

#define BSZ 2
#define LSEQ 2048
#define DIMC 1024
#define HAR 32
#define NH 16
#define HD 64
#define LOG2E 1.4426950408889634f
#define SCALE 0.125f

// ---------------- scratch (__device__ globals; no allocation allowed) ----------------
__device__ __align__(16) float g_res[3 * BSZ * LSEQ * HAR];   // res_q/res_k/res_v
__device__ __align__(16) float g_rkT[BSZ * HAR * LSEQ];       // res_k transposed [B][32][L]
__device__ __align__(16) float g_M[NH * HAR * HAR];           // M_h[i][j] * scale * log2e
__device__ __align__(16) float g_C[NH * HAR * HAR];           // C_h[j][g]
__device__ __align__(16) float g_wo[DIMC * HAR];              // wo[o][g]
__device__ __align__(16) float g_U[BSZ * NH * LSEQ * HAR];    // attention U [B][H][L][32]

typedef unsigned long long u64;

__device__ __forceinline__ u64 pk2(float x, float y) {
    u64 r; asm("mov.b64 %0, {%1,%2};" : "=l"(r) : "f"(x), "f"(y)); return r;
}
__device__ __forceinline__ float2 upk2(u64 a) {
    float2 r; asm("mov.b64 {%0,%1}, %2;" : "=f"(r.x), "=f"(r.y) : "l"(a)); return r;
}
__device__ __forceinline__ u64 fma2(u64 a, u64 b, u64 c) {
    u64 d; asm("fma.rn.f32x2 %0, %1, %2, %3;" : "=l"(d) : "l"(a), "l"(b), "l"(c)); return d;
}
__device__ __forceinline__ u64 add2(u64 a, u64 b) {
    u64 d; asm("add.rn.f32x2 %0, %1, %2;" : "=l"(d) : "l"(a), "l"(b)); return d;
}
__device__ __forceinline__ float ex2f(float x) {
    float r; asm("ex2.approx.ftz.f32 %0, %1;" : "=f"(r) : "f"(x)); return r;
}
__device__ __forceinline__ void cpa16(unsigned dst, const void* src) {
    asm volatile("cp.async.cg.shared.global [%0], [%1], 16;" :: "r"(dst), "l"(src));
}
__device__ __forceinline__ void cpa_commit() {
    asm volatile("cp.async.commit_group;" ::: "memory");
}

// ---------------- K1: per-head M_h and C_h ----------------
__global__ void k_mc(const float* __restrict__ aq, const float* __restrict__ pq,
                     const float* __restrict__ ak, const float* __restrict__ pkh,
                     const float* __restrict__ av, const float* __restrict__ pv,
                     const float* __restrict__ bo) {
    int h = blockIdx.x, t = threadIdx.x;
    __shared__ float wq[HD * HAR], wk[HD * HAR], wv[HD * HAR], bos[HD * HAR];
    for (int e = t; e < HD * HAR; e += 1024) {
        int d = e >> 5, i = e & 31;
        int idx = (h * HD + d) * HAR + i;
        wq[e]  = aq[idx] * (float)cos((double)pq[idx]);   // fp64 cos: immune to fast_math
        wk[e]  = ak[idx] * (float)cos((double)pkh[idx]);
        wv[e]  = av[idx] * (float)cos((double)pv[idx]);
        bos[e] = bo[i * DIMC + h * HD + d];
    }
    __syncthreads();
    int i = t >> 5, j = t & 31;
    float m = 0.f, c = 0.f;
    #pragma unroll 8
    for (int d = 0; d < HD; d++) {
        m += wq[d * 32 + i] * wk[d * 32 + j];
        c += wv[d * 32 + i] * bos[d * 32 + j];
    }
    g_M[h * 1024 + t] = m * (SCALE * LOG2E);
    g_C[h * 1024 + t] = c;
}

// ---------------- K2: wo = amp_o * cos(phase_o) ----------------
__global__ void k_wo(const float* __restrict__ ao, const float* __restrict__ po) {
    int i = blockIdx.x * 1024 + threadIdx.x;
    g_wo[i] = ao[i] * (float)cos((double)po[i]);
}

// ---------------- K3: resonance GEMM  [4096,1024] x [1024,96] (f32x2 packed) ----------------
__global__ __launch_bounds__(256) void k_res(const float* __restrict__ x,
                                             const float* __restrict__ bq,
                                             const float* __restrict__ bk,
                                             const float* __restrict__ bv) {
    __shared__ __align__(16) float Ast[32 * 34];
    __shared__ __align__(16) float Bs[32 * 98];
    int t = threadIdx.x;
    int r0 = blockIdx.x * 32;
    int tx = t & 15, ty = t >> 4;
    u64 acc[2][3];
    #pragma unroll
    for (int u = 0; u < 2; u++)
        #pragma unroll
        for (int cp = 0; cp < 3; cp++) acc[u][cp] = 0ULL;

    for (int k0 = 0; k0 < DIMC; k0 += 32) {
        __syncthreads();
        {
            int row = t >> 3, c4 = (t & 7) * 4;
            float4 v = *(const float4*)(x + (r0 + row) * DIMC + k0 + c4);
            Ast[(c4 + 0) * 34 + row] = v.x;
            Ast[(c4 + 1) * 34 + row] = v.y;
            Ast[(c4 + 2) * 34 + row] = v.z;
            Ast[(c4 + 3) * 34 + row] = v.w;
        }
        for (int f4 = t; f4 < 768; f4 += 256) {
            int n = f4 >> 3, c4 = (f4 & 7) * 4;
            const float* bp = (n < 32) ? (bq + n * DIMC)
                             : (n < 64) ? (bk + (n - 32) * DIMC)
                                        : (bv + (n - 64) * DIMC);
            float4 v = *(const float4*)(bp + k0 + c4);
            Bs[(c4 + 0) * 98 + n] = v.x;
            Bs[(c4 + 1) * 98 + n] = v.y;
            Bs[(c4 + 2) * 98 + n] = v.z;
            Bs[(c4 + 3) * 98 + n] = v.w;
        }
        __syncthreads();
        #pragma unroll
        for (int kk = 0; kk < 32; kk++) {
            float a0 = Ast[kk * 34 + ty * 2];
            float a1 = Ast[kk * 34 + ty * 2 + 1];
            u64 a02 = pk2(a0, a0), a12 = pk2(a1, a1);
            const u64* bp2 = (const u64*)(Bs + kk * 98 + tx * 6);
            #pragma unroll
            for (int cp = 0; cp < 3; cp++) {
                u64 b2 = bp2[cp];
                acc[0][cp] = fma2(a02, b2, acc[0][cp]);
                acc[1][cp] = fma2(a12, b2, acc[1][cp]);
            }
        }
    }
    #pragma unroll
    for (int u = 0; u < 2; u++)
        #pragma unroll
        for (int cp = 0; cp < 3; cp++) {
            float2 f = upk2(acc[u][cp]);
            int row = r0 + ty * 2 + u;
            int b = row >> 11, l = row & (LSEQ - 1);
            #pragma unroll
            for (int j2 = 0; j2 < 2; j2++) {
                int n = tx * 6 + cp * 2 + j2;
                float val = j2 ? f.y : f.x;
                int p = n >> 5, j = n & 31;
                if (p == 1)
                    g_rkT[(b * HAR + j) * LSEQ + l] = val;
                else
                    g_res[((p * BSZ + b) * LSEQ + l) * HAR + j] = val;
            }
        }
}

// ---------------- K4: flash attention, q8 x g16 x k16 split, spill-free ----------------
// lane = qsub*16 + gsub*8 + ksub. 8 queries/lane; gsub splits S j-sum (one
// shfl_xor(8) combine) and PV g-accumulation. Staging loops are unroll-1 with
// loop-carried pointers so ptxas does not hoist address registers.
#define KTBUF (32 * 132)
#define VBUF  (128 * 36)
#define GQPAD 68
__global__ __launch_bounds__(128, 2) void k_attn() {
    extern __shared__ __align__(16) float smem[];
    float* sKT = smem;                        // 2 x KTBUF
    float* sV  = smem + 2 * KTBUF;            // 2 x VBUF
    float* sGq = smem + 2 * KTBUF + 2 * VBUF; // 32 x GQPAD

    int t = threadIdx.x;
    int w = t >> 5, lane = t & 31;
    int qsub = (lane >> 4) & 1;
    int gsub = (lane >> 3) & 1;
    int ksub = lane & 7;
    int q0 = blockIdx.x * 64;
    int bh = blockIdx.y;
    int b = bh >> 4, h = bh & 15;
    const float* rq  = g_res + (0 * BSZ + b) * LSEQ * HAR;
    const float* rv  = g_res + (2 * BSZ + b) * LSEQ * HAR;
    const float* rkT = g_rkT + b * HAR * LSEQ;

    // staging offsets (constants per thread)
    unsigned kbase0 = (unsigned)__cvta_generic_to_shared(sKT);
    unsigned vbase0 = (unsigned)__cvta_generic_to_shared(sV);
    unsigned kdoff = ((t >> 5) * 132 + (t & 31) * 4) * 4;
    int ksoff = (t >> 5) * LSEQ + (t & 31) * 4;
    int p0 = (t & 7) ^ ((t >> 5) & 7);
    unsigned vdoff0 = ((t >> 3) * 36 + p0 * 4) * 4;
    unsigned vdoff1 = ((t >> 3) * 36 + (p0 ^ 4) * 4) * 4 + 2304;
    int vsoff = (t >> 3) * 32 + (t & 7) * 4;

    {   // stage tile 0 into buffer 0
        unsigned kd = kbase0 + kdoff;
        const float* ks = rkT + ksoff;
        #pragma unroll 1
        for (int it = 0; it < 8; it++) { cpa16(kd, ks); kd += 2112; ks += 4 * LSEQ; }
        unsigned vd0 = vbase0 + vdoff0, vd1 = vbase0 + vdoff1;
        const float* vs = rv + vsoff;
        #pragma unroll 1
        for (int it = 0; it < 4; it++) {
            cpa16(vd0, vs); cpa16(vd1, vs + 512);
            vd0 += 4608; vd1 += 4608; vs += 1024;
        }
        cpa_commit();
    }

    {   // Gq[64,32] = rq_tile * M, stored transposed sGq[j][64q]
        int q = t >> 1, jbb = (t & 1) * 16;
        const float* rqrow = rq + (q0 + q) * HAR;
        const float* Mrow = g_M + h * 1024;
        float a[16];
        #pragma unroll
        for (int jj = 0; jj < 16; jj++) a[jj] = 0.f;
        #pragma unroll 4
        for (int i = 0; i < 32; i++) {
            float qv = rqrow[i];
            #pragma unroll
            for (int jj = 0; jj < 16; jj++) a[jj] += qv * Mrow[i * 32 + jbb + jj];
        }
        #pragma unroll
        for (int jj = 0; jj < 16; jj++) sGq[(jbb + jj) * GQPAD + q] = a[jj];
    }

    u64 U2[8][8];                 // [q][16g as 8 u64]
    #pragma unroll
    for (int q = 0; q < 8; q++)
        #pragma unroll
        for (int gp = 0; gp < 8; gp++) U2[q][gp] = 0ULL;
    float lac[8];
    #pragma unroll
    for (int q = 0; q < 8; q++) lac[q] = 0.f;
    int qb = w * 16 + qsub * 8;   // lane's 8 queries (block-local)
    int jb = gsub * 16;           // j half for S
    int gb4 = gsub * 4;           // gi base for PV

    for (int kt = 0; kt < 16; kt++) {
        int cb = kt & 1;
        if (kt < 15) {
            int nb = cb ^ 1;
            unsigned kd = kbase0 + (unsigned)(nb * KTBUF * 4) + kdoff;
            const float* ks = rkT + (kt + 1) * 128 + ksoff;
            #pragma unroll 1
            for (int it = 0; it < 8; it++) { cpa16(kd, ks); kd += 2112; ks += 4 * LSEQ; }
            unsigned vbb = vbase0 + (unsigned)(nb * VBUF * 4);
            unsigned vd0 = vbb + vdoff0, vd1 = vbb + vdoff1;
            const float* vs = rv + (kt + 1) * 128 * HAR + vsoff;
            #pragma unroll 1
            for (int it = 0; it < 4; it++) {
                cpa16(vd0, vs); cpa16(vd1, vs + 512);
                vd0 += 4608; vd1 += 4608; vs += 1024;
            }
            cpa_commit();
            asm volatile("cp.async.wait_group 1;" ::: "memory");
        } else {
            asm volatile("cp.async.wait_group 0;" ::: "memory");
        }
        __syncthreads();

        const float* ktb = sKT + cb * KTBUF;
        const float* vtb = sV + cb * VBUF;

        #pragma unroll
        for (int hp = 0; hp < 2; hp++) {          // half-pass: 8 keys/lane
            // ---- S phase (j half): s2[8q][4 u64 = 8 keys] ----
            u64 s2[8][4];
            #pragma unroll
            for (int q = 0; q < 8; q++)
                #pragma unroll
                for (int kp = 0; kp < 4; kp++) s2[q][kp] = 0ULL;
            #pragma unroll 2
            for (int kk = 0; kk < 16; kk++) {
                int j = jb + kk;
                const float* gqp = sGq + j * GQPAD + qb;
                float4 gq0 = *(const float4*)(gqp);
                float4 gq1 = *(const float4*)(gqp + 4);
                const float* kr = ktb + j * 132 + ksub * 4 + hp * 64;
                ulonglong2 kva = *(const ulonglong2*)(kr);
                ulonglong2 kvb = *(const ulonglong2*)(kr + 32);
                u64 a;
                a = pk2(gq0.x, gq0.x);
                s2[0][0]=fma2(a,kva.x,s2[0][0]); s2[0][1]=fma2(a,kva.y,s2[0][1]);
                s2[0][2]=fma2(a,kvb.x,s2[0][2]); s2[0][3]=fma2(a,kvb.y,s2[0][3]);
                a = pk2(gq0.y, gq0.y);
                s2[1][0]=fma2(a,kva.x,s2[1][0]); s2[1][1]=fma2(a,kva.y,s2[1][1]);
                s2[1][2]=fma2(a,kvb.x,s2[1][2]); s2[1][3]=fma2(a,kvb.y,s2[1][3]);
                a = pk2(gq0.z, gq0.z);
                s2[2][0]=fma2(a,kva.x,s2[2][0]); s2[2][1]=fma2(a,kva.y,s2[2][1]);
                s2[2][2]=fma2(a,kvb.x,s2[2][2]); s2[2][3]=fma2(a,kvb.y,s2[2][3]);
                a = pk2(gq0.w, gq0.w);
                s2[3][0]=fma2(a,kva.x,s2[3][0]); s2[3][1]=fma2(a,kva.y,s2[3][1]);
                s2[3][2]=fma2(a,kvb.x,s2[3][2]); s2[3][3]=fma2(a,kvb.y,s2[3][3]);
                a = pk2(gq1.x, gq1.x);
                s2[4][0]=fma2(a,kva.x,s2[4][0]); s2[4][1]=fma2(a,kva.y,s2[4][1]);
                s2[4][2]=fma2(a,kvb.x,s2[4][2]); s2[4][3]=fma2(a,kvb.y,s2[4][3]);
                a = pk2(gq1.y, gq1.y);
                s2[5][0]=fma2(a,kva.x,s2[5][0]); s2[5][1]=fma2(a,kva.y,s2[5][1]);
                s2[5][2]=fma2(a,kvb.x,s2[5][2]); s2[5][3]=fma2(a,kvb.y,s2[5][3]);
                a = pk2(gq1.z, gq1.z);
                s2[6][0]=fma2(a,kva.x,s2[6][0]); s2[6][1]=fma2(a,kva.y,s2[6][1]);
                s2[6][2]=fma2(a,kvb.x,s2[6][2]); s2[6][3]=fma2(a,kvb.y,s2[6][3]);
                a = pk2(gq1.w, gq1.w);
                s2[7][0]=fma2(a,kva.x,s2[7][0]); s2[7][1]=fma2(a,kva.y,s2[7][1]);
                s2[7][2]=fma2(a,kvb.x,s2[7][2]); s2[7][3]=fma2(a,kvb.y,s2[7][3]);
            }
            // ---- combine j halves across gsub (xor 8), then exp ----
            #pragma unroll
            for (int q = 0; q < 8; q++) {
                #pragma unroll
                for (int kp = 0; kp < 4; kp++) {
                    u64 o = __shfl_xor_sync(0xffffffffu, s2[q][kp], 8);
                    u64 s = add2(s2[q][kp], o);
                    float2 f = upk2(s);
                    float px = ex2f(f.x), py = ex2f(f.y);
                    s2[q][kp] = pk2(px, py);
                    lac[q] += px + py;
                }
            }
            // ---- PV phase: key-outer, vv preloaded; U[8q][16g-half] += p*V ----
            #pragma unroll
            for (int tt = 0; tt < 2; tt++) {
                #pragma unroll
                for (int jp = 0; jp < 2; jp++) {
                    #pragma unroll
                    for (int j2 = 0; j2 < 2; j2++) {
                        int key = ksub * 4 + hp * 64 + tt * 32 + jp * 2 + j2;
                        const float* vr = vtb + key * 36;
                        ulonglong2 vv0 = *(const ulonglong2*)(vr + (((gb4 + 0) ^ ksub) << 2));
                        ulonglong2 vv1 = *(const ulonglong2*)(vr + (((gb4 + 1) ^ ksub) << 2));
                        ulonglong2 vv2 = *(const ulonglong2*)(vr + (((gb4 + 2) ^ ksub) << 2));
                        ulonglong2 vv3 = *(const ulonglong2*)(vr + (((gb4 + 3) ^ ksub) << 2));
                        #pragma unroll
                        for (int q = 0; q < 8; q++) {
                            float2 f = upk2(s2[q][tt * 2 + jp]);
                            float p = j2 ? f.y : f.x;
                            u64 a = pk2(p, p);
                            U2[q][0] = fma2(a, vv0.x, U2[q][0]);
                            U2[q][1] = fma2(a, vv0.y, U2[q][1]);
                            U2[q][2] = fma2(a, vv1.x, U2[q][2]);
                            U2[q][3] = fma2(a, vv1.y, U2[q][3]);
                            U2[q][4] = fma2(a, vv2.x, U2[q][4]);
                            U2[q][5] = fma2(a, vv2.y, U2[q][5]);
                            U2[q][6] = fma2(a, vv3.x, U2[q][6]);
                            U2[q][7] = fma2(a, vv3.y, U2[q][7]);
                        }
                    }
                }
            }
        }
        __syncthreads();
    }

    // ---- final: butterfly-reduce U and lac over the 8 ksub lanes ----
    #pragma unroll
    for (int d = 1; d <= 4; d <<= 1) {
        #pragma unroll
        for (int q = 0; q < 8; q++) {
            lac[q] += __shfl_xor_sync(0xffffffffu, lac[q], d);
            #pragma unroll
            for (int gp = 0; gp < 8; gp++) {
                u64 o = __shfl_xor_sync(0xffffffffu, U2[q][gp], d);
                U2[q][gp] = add2(U2[q][gp], o);
            }
        }
    }
    {   // lane ksub writes query qb+ksub, its 16-g half
        int q = ksub;
        float inv = 1.f / lac[q];
        float* up = g_U + (bh * LSEQ + q0 + qb + q) * HAR + gsub * 16;
        #pragma unroll
        for (int g4 = 0; g4 < 4; g4++) {
            float2 A = upk2(U2[q][g4 * 2]), B2 = upk2(U2[q][g4 * 2 + 1]);
            *(float4*)(up + g4 * 4) =
                make_float4(A.x * inv, A.y * inv, B2.x * inv, B2.y * inv);
        }
    }
}

// ---------------- K5 (fused mix+out): 16 rows/block ----------------
__global__ __launch_bounds__(256) void k_mixout(float* __restrict__ out) {
    __shared__ __align__(16) float sU[16 * 512];
    __shared__ __align__(16) float sR[16 * 32];
    int t = threadIdx.x;
    int row0 = blockIdx.x * 16;
    int b = row0 >> 11, l0 = row0 & (LSEQ - 1);
    for (int idx = t; idx < 16 * 512; idx += 256) {
        int r = idx >> 9, rest = idx & 511;
        int h = rest >> 5, j = rest & 31;
        sU[idx] = g_U[((b * NH + h) * LSEQ + (l0 + r)) * HAR + j];
    }
    __syncthreads();
    {
        int rp = t >> 5, g = t & 31;
        const float* cp = g_C;
        const float* u0 = sU + (2 * rp) * 512;
        const float* u1 = sU + (2 * rp + 1) * 512;
        u64 acc = 0ULL;
        #pragma unroll 8
        for (int e = 0; e < 512; e++) {
            u64 av = pk2(u0[e], u1[e]);
            float c = cp[e * 32 + g];
            acc = fma2(av, pk2(c, c), acc);
        }
        float2 f = upk2(acc);
        sR[(2 * rp) * 32 + g] = f.x;
        sR[(2 * rp + 1) * 32 + g] = f.y;
    }
    __syncthreads();
    for (int o = t; o < DIMC; o += 256) {
        const u64* wp = (const u64*)(g_wo + o * 32);
        u64 w2[16];
        #pragma unroll
        for (int gp = 0; gp < 16; gp++) w2[gp] = wp[gp];
        #pragma unroll 4
        for (int r = 0; r < 16; r++) {
            const u64* sp = (const u64*)(sR + r * 32);
            u64 acc = 0ULL;
            #pragma unroll
            for (int gp = 0; gp < 16; gp++) acc = fma2(sp[gp], w2[gp], acc);
            float2 f = upk2(acc);
            out[(row0 + r) * DIMC + o] = f.x + f.y;
        }
    }
}

extern "C" void kernel_launch(void* const* d_in, const int* in_sizes, int n_in,
                              void* d_out, int out_size) {
    const float* x   = (const float*)d_in[0];
    const float* bq  = (const float*)d_in[1];
    const float* pq  = (const float*)d_in[2];
    const float* aq  = (const float*)d_in[3];
    const float* bk  = (const float*)d_in[4];
    const float* pk_ = (const float*)d_in[5];
    const float* ak  = (const float*)d_in[6];
    const float* bv  = (const float*)d_in[7];
    const float* pv  = (const float*)d_in[8];
    const float* av  = (const float*)d_in[9];
    const float* bo  = (const float*)d_in[10];
    const float* po  = (const float*)d_in[11];
    const float* ao  = (const float*)d_in[12];
    float* out = (float*)d_out;

    const int attn_smem = (2 * KTBUF + 2 * VBUF + 32 * GQPAD) * (int)sizeof(float);
    cudaFuncSetAttribute(k_attn, cudaFuncAttributeMaxDynamicSharedMemorySize, attn_smem);

    k_mc<<<NH, 1024>>>(aq, pq, ak, pk_, av, pv, bo);
    k_wo<<<32, 1024>>>(ao, po);
    k_res<<<BSZ * LSEQ / 32, 256>>>(x, bq, bk, bv);
    k_attn<<<dim3(LSEQ / 64, BSZ * NH), 128, attn_smem>>>();
    k_mixout<<<BSZ * LSEQ / 16, 256>>>(out);
}

// round 15
// speedup vs baseline: 1.1248x; 1.1248x over previous
#include <cuda_runtime.h>

#define BSZ 2
#define LSEQ 2048
#define DIMC 1024
#define HAR 32
#define NH 16
#define HD 64
#define LOG2E 1.4426950408889634f
#define SCALE 0.125f

// ---------------- scratch (__device__ globals; no allocation allowed) ----------------
__device__ __align__(16) float g_res[3 * BSZ * LSEQ * HAR];   // res_q/res_k/res_v
__device__ __align__(16) float g_rkT[BSZ * HAR * LSEQ];       // res_k transposed [B][32][L]
__device__ __align__(16) float g_M[NH * HAR * HAR];           // M_h[i][j] * scale * log2e
__device__ __align__(16) float g_C[NH * HAR * HAR];           // C_h[j][g]
__device__ __align__(16) float g_wo[DIMC * HAR];              // wo[o][g]
__device__ __align__(16) float g_U[BSZ * NH * LSEQ * HAR];    // attention U [B][H][L][32]

typedef unsigned long long u64;

__device__ __forceinline__ u64 pk2(float x, float y) {
    u64 r; asm("mov.b64 %0, {%1,%2};" : "=l"(r) : "f"(x), "f"(y)); return r;
}
__device__ __forceinline__ float2 upk2(u64 a) {
    float2 r; asm("mov.b64 {%0,%1}, %2;" : "=f"(r.x), "=f"(r.y) : "l"(a)); return r;
}
__device__ __forceinline__ u64 fma2(u64 a, u64 b, u64 c) {
    u64 d; asm("fma.rn.f32x2 %0, %1, %2, %3;" : "=l"(d) : "l"(a), "l"(b), "l"(c)); return d;
}
__device__ __forceinline__ u64 add2(u64 a, u64 b) {
    u64 d; asm("add.rn.f32x2 %0, %1, %2;" : "=l"(d) : "l"(a), "l"(b)); return d;
}
__device__ __forceinline__ float ex2f(float x) {
    float r; asm("ex2.approx.ftz.f32 %0, %1;" : "=f"(r) : "f"(x)); return r;
}
__device__ __forceinline__ void cpa16(unsigned dst, const void* src) {
    asm volatile("cp.async.cg.shared.global [%0], [%1], 16;" :: "r"(dst), "l"(src));
}
__device__ __forceinline__ void cpa_commit() {
    asm volatile("cp.async.commit_group;" ::: "memory");
}

// ---------------- K1: per-head M_h and C_h ----------------
__global__ void k_mc(const float* __restrict__ aq, const float* __restrict__ pq,
                     const float* __restrict__ ak, const float* __restrict__ pkh,
                     const float* __restrict__ av, const float* __restrict__ pv,
                     const float* __restrict__ bo) {
    int h = blockIdx.x, t = threadIdx.x;
    __shared__ float wq[HD * HAR], wk[HD * HAR], wv[HD * HAR], bos[HD * HAR];
    for (int e = t; e < HD * HAR; e += 1024) {
        int d = e >> 5, i = e & 31;
        int idx = (h * HD + d) * HAR + i;
        wq[e]  = aq[idx] * (float)cos((double)pq[idx]);   // fp64 cos: immune to fast_math
        wk[e]  = ak[idx] * (float)cos((double)pkh[idx]);
        wv[e]  = av[idx] * (float)cos((double)pv[idx]);
        bos[e] = bo[i * DIMC + h * HD + d];
    }
    __syncthreads();
    int i = t >> 5, j = t & 31;
    float m = 0.f, c = 0.f;
    #pragma unroll 8
    for (int d = 0; d < HD; d++) {
        m += wq[d * 32 + i] * wk[d * 32 + j];
        c += wv[d * 32 + i] * bos[d * 32 + j];
    }
    g_M[h * 1024 + t] = m * (SCALE * LOG2E);
    g_C[h * 1024 + t] = c;
}

// ---------------- K2: wo = amp_o * cos(phase_o) ----------------
__global__ void k_wo(const float* __restrict__ ao, const float* __restrict__ po) {
    int i = blockIdx.x * 1024 + threadIdx.x;
    g_wo[i] = ao[i] * (float)cos((double)po[i]);
}

// ---------------- K3: resonance GEMM  [4096,1024] x [1024,96] (f32x2 packed) ----------------
__global__ __launch_bounds__(256) void k_res(const float* __restrict__ x,
                                             const float* __restrict__ bq,
                                             const float* __restrict__ bk,
                                             const float* __restrict__ bv) {
    __shared__ __align__(16) float Ast[32 * 34];
    __shared__ __align__(16) float Bs[32 * 98];
    int t = threadIdx.x;
    int r0 = blockIdx.x * 32;
    int tx = t & 15, ty = t >> 4;
    u64 acc[2][3];
    #pragma unroll
    for (int u = 0; u < 2; u++)
        #pragma unroll
        for (int cp = 0; cp < 3; cp++) acc[u][cp] = 0ULL;

    for (int k0 = 0; k0 < DIMC; k0 += 32) {
        __syncthreads();
        {
            int row = t >> 3, c4 = (t & 7) * 4;
            float4 v = *(const float4*)(x + (r0 + row) * DIMC + k0 + c4);
            Ast[(c4 + 0) * 34 + row] = v.x;
            Ast[(c4 + 1) * 34 + row] = v.y;
            Ast[(c4 + 2) * 34 + row] = v.z;
            Ast[(c4 + 3) * 34 + row] = v.w;
        }
        for (int f4 = t; f4 < 768; f4 += 256) {
            int n = f4 >> 3, c4 = (f4 & 7) * 4;
            const float* bp = (n < 32) ? (bq + n * DIMC)
                             : (n < 64) ? (bk + (n - 32) * DIMC)
                                        : (bv + (n - 64) * DIMC);
            float4 v = *(const float4*)(bp + k0 + c4);
            Bs[(c4 + 0) * 98 + n] = v.x;
            Bs[(c4 + 1) * 98 + n] = v.y;
            Bs[(c4 + 2) * 98 + n] = v.z;
            Bs[(c4 + 3) * 98 + n] = v.w;
        }
        __syncthreads();
        #pragma unroll
        for (int kk = 0; kk < 32; kk++) {
            float a0 = Ast[kk * 34 + ty * 2];
            float a1 = Ast[kk * 34 + ty * 2 + 1];
            u64 a02 = pk2(a0, a0), a12 = pk2(a1, a1);
            const u64* bp2 = (const u64*)(Bs + kk * 98 + tx * 6);
            #pragma unroll
            for (int cp = 0; cp < 3; cp++) {
                u64 b2 = bp2[cp];
                acc[0][cp] = fma2(a02, b2, acc[0][cp]);
                acc[1][cp] = fma2(a12, b2, acc[1][cp]);
            }
        }
    }
    #pragma unroll
    for (int u = 0; u < 2; u++)
        #pragma unroll
        for (int cp = 0; cp < 3; cp++) {
            float2 f = upk2(acc[u][cp]);
            int row = r0 + ty * 2 + u;
            int b = row >> 11, l = row & (LSEQ - 1);
            #pragma unroll
            for (int j2 = 0; j2 < 2; j2++) {
                int n = tx * 6 + cp * 2 + j2;
                float val = j2 ? f.y : f.x;
                int p = n >> 5, j = n & 31;
                if (p == 1)
                    g_rkT[(b * HAR + j) * LSEQ + l] = val;
                else
                    g_res[((p * BSZ + b) * LSEQ + l) * HAR + j] = val;
            }
        }
}

// ---------------- K4: flash attention, q4 x g2 x k4 lane split, 3 CTAs/SM ----------------
// lane = qsub*8 + gsub*4 + ksub. 4 queries/lane, 32 keys/lane (4 sub-passes of 8),
// gsub halves BOTH the S j-sum (combined by shfl_xor(4); both partners get p) and
// the PV g-accumulation. U2 = 4q x 16g = 64 regs; s2 = 16 u64 = 32 regs.
// j-map (kk&3)+4*gsub+8*(kk>>2) makes K chunk bank-slots {ksub} u {4+ksub} distinct.
// V stride 32: gi^sw swizzle is injective over (gsub,ksub) -> conflict-free.
#define KTBUF (32 * 132)
#define VBUF  (128 * 32)
#define GQSTR 64
__global__ __launch_bounds__(128, 3) void k_attn() {
    extern __shared__ __align__(16) float smem[];
    float* sKT = smem;                        // 2 x KTBUF
    float* sV  = smem + 2 * KTBUF;            // 2 x VBUF
    float* sGq = smem + 2 * KTBUF + 2 * VBUF; // 32 x 64 (j-rotated)

    int t = threadIdx.x;
    int w = t >> 5, lane = t & 31;
    int qsub = (lane >> 3) & 3;
    int gsub = (lane >> 2) & 1;
    int ksub = lane & 3;
    int q0 = blockIdx.x * 64;
    int bh = blockIdx.y;
    int b = bh >> 4, h = bh & 15;
    const float* rq  = g_res + (0 * BSZ + b) * LSEQ * HAR;
    const float* rv  = g_res + (2 * BSZ + b) * LSEQ * HAR;
    const float* rkT = g_rkT + b * HAR * LSEQ;

    // staging offsets (constants per thread)
    unsigned kbase0 = (unsigned)__cvta_generic_to_shared(sKT);
    unsigned vbase0 = (unsigned)__cvta_generic_to_shared(sV);
    unsigned kdoff = ((t >> 5) * 132 + (t & 31) * 4) * 4;
    int ksoff = (t >> 5) * LSEQ + (t & 31) * 4;
    int p0 = (t & 7) ^ (t >> 5);
    unsigned vdoff0 = ((t >> 3) * 32 + (p0 & 7) * 4) * 4;
    unsigned vdoff1 = ((t >> 3) * 32 + ((p0 ^ 4) & 7) * 4) * 4 + 2048;
    int vsoff = (t >> 3) * 32 + (t & 7) * 4;

    {   // stage tile 0 into buffer 0
        unsigned kd = kbase0 + kdoff;
        const float* ks = rkT + ksoff;
        #pragma unroll 1
        for (int it = 0; it < 8; it++) { cpa16(kd, ks); kd += 2112; ks += 4 * LSEQ; }
        unsigned vd0 = vbase0 + vdoff0, vd1 = vbase0 + vdoff1;
        const float* vs = rv + vsoff;
        #pragma unroll 1
        for (int it = 0; it < 4; it++) {
            cpa16(vd0, vs); cpa16(vd1, vs + 512);
            vd0 += 4096; vd1 += 4096; vs += 1024;
        }
        cpa_commit();
    }

    {   // phase 0: Gq[64,32] = rq_tile * M, stored j-major with 4-float rotation
        int q = t >> 1, jbb = (t & 1) * 16;
        const float* rqrow = rq + (q0 + q) * HAR;
        const float* Mrow = g_M + h * 1024;
        float a[16];
        #pragma unroll
        for (int jj = 0; jj < 16; jj++) a[jj] = 0.f;
        #pragma unroll 4
        for (int i = 0; i < 32; i++) {
            float qv = rqrow[i];
            #pragma unroll
            for (int jj = 0; jj < 16; jj++) a[jj] += qv * Mrow[i * 32 + jbb + jj];
        }
        #pragma unroll
        for (int jj = 0; jj < 16; jj++) {
            int j = jbb + jj;
            sGq[j * GQSTR + ((q + 4 * (j & 7)) & 63)] = a[jj];
        }
    }

    u64 U2[4][8];                 // [q][16g as 8 u64]
    #pragma unroll
    for (int q = 0; q < 4; q++)
        #pragma unroll
        for (int gp = 0; gp < 8; gp++) U2[q][gp] = 0ULL;
    float lac[4];
    #pragma unroll
    for (int q = 0; q < 4; q++) lac[q] = 0.f;
    int qb = w * 16 + qsub * 4;   // lane's 4 queries (block-local)
    int gsub4 = gsub * 4;

    for (int kt = 0; kt < 16; kt++) {
        int cb = kt & 1;
        if (kt < 15) {
            int nb = cb ^ 1;
            unsigned kd = kbase0 + (unsigned)(nb * KTBUF * 4) + kdoff;
            const float* ks = rkT + (kt + 1) * 128 + ksoff;
            #pragma unroll 1
            for (int it = 0; it < 8; it++) { cpa16(kd, ks); kd += 2112; ks += 4 * LSEQ; }
            unsigned vbb = vbase0 + (unsigned)(nb * VBUF * 4);
            unsigned vd0 = vbb + vdoff0, vd1 = vbb + vdoff1;
            const float* vs = rv + (kt + 1) * 128 * HAR + vsoff;
            #pragma unroll 1
            for (int it = 0; it < 4; it++) {
                cpa16(vd0, vs); cpa16(vd1, vs + 512);
                vd0 += 4096; vd1 += 4096; vs += 1024;
            }
            cpa_commit();
            asm volatile("cp.async.wait_group 1;" ::: "memory");
        } else {
            asm volatile("cp.async.wait_group 0;" ::: "memory");
        }
        __syncthreads();

        const float* ktb = sKT + cb * KTBUF;
        const float* vtb = sV + cb * VBUF;

        #pragma unroll
        for (int sp = 0; sp < 4; sp++) {          // sub-pass: 8 keys/lane
            // ---- S phase (j half): s2[4q][2 chunks x 2] over 8 keys ----
            u64 s2[4][4];
            #pragma unroll
            for (int q = 0; q < 4; q++)
                #pragma unroll
                for (int kp = 0; kp < 4; kp++) s2[q][kp] = 0ULL;
            #pragma unroll 4
            for (int kk = 0; kk < 16; kk++) {
                int j = (kk & 3) + gsub4 + ((kk >> 2) << 3);
                float4 gq = *(const float4*)(sGq + j * GQSTR + ((qb + 4 * (j & 7)) & 63));
                const float* kr = ktb + j * 132 + ksub * 4 + sp * 32;
                ulonglong2 kva = *(const ulonglong2*)(kr);
                ulonglong2 kvb = *(const ulonglong2*)(kr + 16);
                u64 a;
                a = pk2(gq.x, gq.x);
                s2[0][0] = fma2(a, kva.x, s2[0][0]); s2[0][1] = fma2(a, kva.y, s2[0][1]);
                s2[0][2] = fma2(a, kvb.x, s2[0][2]); s2[0][3] = fma2(a, kvb.y, s2[0][3]);
                a = pk2(gq.y, gq.y);
                s2[1][0] = fma2(a, kva.x, s2[1][0]); s2[1][1] = fma2(a, kva.y, s2[1][1]);
                s2[1][2] = fma2(a, kvb.x, s2[1][2]); s2[1][3] = fma2(a, kvb.y, s2[1][3]);
                a = pk2(gq.z, gq.z);
                s2[2][0] = fma2(a, kva.x, s2[2][0]); s2[2][1] = fma2(a, kva.y, s2[2][1]);
                s2[2][2] = fma2(a, kvb.x, s2[2][2]); s2[2][3] = fma2(a, kvb.y, s2[2][3]);
                a = pk2(gq.w, gq.w);
                s2[3][0] = fma2(a, kva.x, s2[3][0]); s2[3][1] = fma2(a, kva.y, s2[3][1]);
                s2[3][2] = fma2(a, kvb.x, s2[3][2]); s2[3][3] = fma2(a, kvb.y, s2[3][3]);
            }
            // ---- combine j halves across gsub (xor 4), then exp ----
            #pragma unroll
            for (int q = 0; q < 4; q++) {
                #pragma unroll
                for (int kp = 0; kp < 4; kp++) {
                    u64 o = __shfl_xor_sync(0xffffffffu, s2[q][kp], 4);
                    u64 s = add2(s2[q][kp], o);
                    float2 f = upk2(s);
                    float px = ex2f(f.x), py = ex2f(f.y);
                    s2[q][kp] = pk2(px, py);
                    lac[q] += px + py;
                }
            }
            // ---- PV phase: U[4q][16g-half] += p * V ----
            #pragma unroll
            for (int cl = 0; cl < 2; cl++) {
                int sw = (ksub + 4 * cl) & 7;
                #pragma unroll
                for (int kj = 0; kj < 4; kj++) {
                    int key = ksub * 4 + (sp * 2 + cl) * 16 + kj;
                    const float* vr = vtb + key * 32;
                    ulonglong2 vv0 = *(const ulonglong2*)(vr + (((gsub4 + 0) ^ sw) << 2));
                    ulonglong2 vv1 = *(const ulonglong2*)(vr + (((gsub4 + 1) ^ sw) << 2));
                    ulonglong2 vv2 = *(const ulonglong2*)(vr + (((gsub4 + 2) ^ sw) << 2));
                    ulonglong2 vv3 = *(const ulonglong2*)(vr + (((gsub4 + 3) ^ sw) << 2));
                    #pragma unroll
                    for (int q = 0; q < 4; q++) {
                        float2 f = upk2(s2[q][cl * 2 + (kj >> 1)]);
                        float p = (kj & 1) ? f.y : f.x;
                        u64 a = pk2(p, p);
                        U2[q][0] = fma2(a, vv0.x, U2[q][0]);
                        U2[q][1] = fma2(a, vv0.y, U2[q][1]);
                        U2[q][2] = fma2(a, vv1.x, U2[q][2]);
                        U2[q][3] = fma2(a, vv1.y, U2[q][3]);
                        U2[q][4] = fma2(a, vv2.x, U2[q][4]);
                        U2[q][5] = fma2(a, vv2.y, U2[q][5]);
                        U2[q][6] = fma2(a, vv3.x, U2[q][6]);
                        U2[q][7] = fma2(a, vv3.y, U2[q][7]);
                    }
                }
            }
        }
        __syncthreads();
    }

    // ---- final: butterfly-reduce U and lac over the 4 ksub lanes (xor 1, 2) ----
    #pragma unroll
    for (int d = 1; d <= 2; d <<= 1) {
        #pragma unroll
        for (int q = 0; q < 4; q++) {
            lac[q] += __shfl_xor_sync(0xffffffffu, lac[q], d);
            #pragma unroll
            for (int gp = 0; gp < 8; gp++) {
                u64 o = __shfl_xor_sync(0xffffffffu, U2[q][gp], d);
                U2[q][gp] = add2(U2[q][gp], o);
            }
        }
    }
    {   // lane (qsub,gsub,ksub) writes query qb+ksub, g-half gsub
        int q = ksub;
        float inv = 1.f / lac[q];
        float* up = g_U + (bh * LSEQ + q0 + qb + q) * HAR + gsub * 16;
        #pragma unroll
        for (int g4 = 0; g4 < 4; g4++) {
            float2 A = upk2(U2[q][g4 * 2]), B2 = upk2(U2[q][g4 * 2 + 1]);
            *(float4*)(up + g4 * 4) =
                make_float4(A.x * inv, A.y * inv, B2.x * inv, B2.y * inv);
        }
    }
}

// ---------------- K5 (fused mix+out): 16 rows/block ----------------
__global__ __launch_bounds__(256) void k_mixout(float* __restrict__ out) {
    __shared__ __align__(16) float sU[16 * 512];
    __shared__ __align__(16) float sR[16 * 32];
    int t = threadIdx.x;
    int row0 = blockIdx.x * 16;
    int b = row0 >> 11, l0 = row0 & (LSEQ - 1);
    for (int idx = t; idx < 16 * 512; idx += 256) {
        int r = idx >> 9, rest = idx & 511;
        int h = rest >> 5, j = rest & 31;
        sU[idx] = g_U[((b * NH + h) * LSEQ + (l0 + r)) * HAR + j];
    }
    __syncthreads();
    {
        int rp = t >> 5, g = t & 31;
        const float* cp = g_C;
        const float* u0 = sU + (2 * rp) * 512;
        const float* u1 = sU + (2 * rp + 1) * 512;
        u64 acc = 0ULL;
        #pragma unroll 8
        for (int e = 0; e < 512; e++) {
            u64 av = pk2(u0[e], u1[e]);
            float c = cp[e * 32 + g];
            acc = fma2(av, pk2(c, c), acc);
        }
        float2 f = upk2(acc);
        sR[(2 * rp) * 32 + g] = f.x;
        sR[(2 * rp + 1) * 32 + g] = f.y;
    }
    __syncthreads();
    for (int o = t; o < DIMC; o += 256) {
        const u64* wp = (const u64*)(g_wo + o * 32);
        u64 w2[16];
        #pragma unroll
        for (int gp = 0; gp < 16; gp++) w2[gp] = wp[gp];
        #pragma unroll 4
        for (int r = 0; r < 16; r++) {
            const u64* sp = (const u64*)(sR + r * 32);
            u64 acc = 0ULL;
            #pragma unroll
            for (int gp = 0; gp < 16; gp++) acc = fma2(sp[gp], w2[gp], acc);
            float2 f = upk2(acc);
            out[(row0 + r) * DIMC + o] = f.x + f.y;
        }
    }
}

extern "C" void kernel_launch(void* const* d_in, const int* in_sizes, int n_in,
                              void* d_out, int out_size) {
    const float* x   = (const float*)d_in[0];
    const float* bq  = (const float*)d_in[1];
    const float* pq  = (const float*)d_in[2];
    const float* aq  = (const float*)d_in[3];
    const float* bk  = (const float*)d_in[4];
    const float* pk_ = (const float*)d_in[5];
    const float* ak  = (const float*)d_in[6];
    const float* bv  = (const float*)d_in[7];
    const float* pv  = (const float*)d_in[8];
    const float* av  = (const float*)d_in[9];
    const float* bo  = (const float*)d_in[10];
    const float* po  = (const float*)d_in[11];
    const float* ao  = (const float*)d_in[12];
    float* out = (float*)d_out;

    const int attn_smem = (2 * KTBUF + 2 * VBUF + 32 * GQSTR) * (int)sizeof(float);
    cudaFuncSetAttribute(k_attn, cudaFuncAttributeMaxDynamicSharedMemorySize, attn_smem);

    k_mc<<<NH, 1024>>>(aq, pq, ak, pk_, av, pv, bo);
    k_wo<<<32, 1024>>>(ao, po);
    k_res<<<BSZ * LSEQ / 32, 256>>>(x, bq, bk, bv);
    k_attn<<<dim3(LSEQ / 64, BSZ * NH), 128, attn_smem>>>();
    k_mixout<<<BSZ * LSEQ / 16, 256>>>(out);
}

// round 16
// speedup vs baseline: 1.2275x; 1.0912x over previous
#include <cuda_runtime.h>

#define BSZ 2
#define LSEQ 2048
#define DIMC 1024
#define HAR 32
#define NH 16
#define HD 64
#define LOG2E 1.4426950408889634f
#define SCALE 0.125f

// ---------------- scratch (__device__ globals; no allocation allowed) ----------------
__device__ __align__(16) float g_res[3 * BSZ * LSEQ * HAR];   // res_q/res_k/res_v
__device__ __align__(16) float g_rkT[BSZ * HAR * LSEQ];       // res_k transposed [B][32][L]
__device__ __align__(16) float g_M[NH * HAR * HAR];           // M_h[i][j] * scale * log2e
__device__ __align__(16) float g_C[NH * HAR * HAR];           // C_h[j][g]
__device__ __align__(16) float g_wo[DIMC * HAR];              // wo[o][g]
__device__ __align__(16) float g_U[BSZ * NH * LSEQ * HAR];    // attention U [B][H][L][32]

typedef unsigned long long u64;

__device__ __forceinline__ u64 pk2(float x, float y) {
    u64 r; asm("mov.b64 %0, {%1,%2};" : "=l"(r) : "f"(x), "f"(y)); return r;
}
__device__ __forceinline__ float2 upk2(u64 a) {
    float2 r; asm("mov.b64 {%0,%1}, %2;" : "=f"(r.x), "=f"(r.y) : "l"(a)); return r;
}
__device__ __forceinline__ u64 fma2(u64 a, u64 b, u64 c) {
    u64 d; asm("fma.rn.f32x2 %0, %1, %2, %3;" : "=l"(d) : "l"(a), "l"(b), "l"(c)); return d;
}
__device__ __forceinline__ u64 add2(u64 a, u64 b) {
    u64 d; asm("add.rn.f32x2 %0, %1, %2;" : "=l"(d) : "l"(a), "l"(b)); return d;
}
__device__ __forceinline__ float ex2f(float x) {
    float r; asm("ex2.approx.ftz.f32 %0, %1;" : "=f"(r) : "f"(x)); return r;
}
__device__ __forceinline__ void cpa16(unsigned dst, const void* src) {
    asm volatile("cp.async.cg.shared.global [%0], [%1], 16;" :: "r"(dst), "l"(src));
}
__device__ __forceinline__ void cpa_commit() {
    asm volatile("cp.async.commit_group;" ::: "memory");
}

// ---------------- K1: per-head M_h and C_h ----------------
__global__ void k_mc(const float* __restrict__ aq, const float* __restrict__ pq,
                     const float* __restrict__ ak, const float* __restrict__ pkh,
                     const float* __restrict__ av, const float* __restrict__ pv,
                     const float* __restrict__ bo) {
    int h = blockIdx.x, t = threadIdx.x;
    __shared__ float wq[HD * HAR], wk[HD * HAR], wv[HD * HAR], bos[HD * HAR];
    for (int e = t; e < HD * HAR; e += 1024) {
        int d = e >> 5, i = e & 31;
        int idx = (h * HD + d) * HAR + i;
        wq[e]  = aq[idx] * (float)cos((double)pq[idx]);   // fp64 cos: immune to fast_math
        wk[e]  = ak[idx] * (float)cos((double)pkh[idx]);
        wv[e]  = av[idx] * (float)cos((double)pv[idx]);
        bos[e] = bo[i * DIMC + h * HD + d];
    }
    __syncthreads();
    int i = t >> 5, j = t & 31;
    float m = 0.f, c = 0.f;
    #pragma unroll 8
    for (int d = 0; d < HD; d++) {
        m += wq[d * 32 + i] * wk[d * 32 + j];
        c += wv[d * 32 + i] * bos[d * 32 + j];
    }
    g_M[h * 1024 + t] = m * (SCALE * LOG2E);
    g_C[h * 1024 + t] = c;
}

// ---------------- K2: wo = amp_o * cos(phase_o) ----------------
__global__ void k_wo(const float* __restrict__ ao, const float* __restrict__ po) {
    int i = blockIdx.x * 1024 + threadIdx.x;
    g_wo[i] = ao[i] * (float)cos((double)po[i]);
}

// ---------------- K3: resonance GEMM  [4096,1024] x [1024,96] (f32x2 packed) ----------------
__global__ __launch_bounds__(256) void k_res(const float* __restrict__ x,
                                             const float* __restrict__ bq,
                                             const float* __restrict__ bk,
                                             const float* __restrict__ bv) {
    __shared__ __align__(16) float Ast[32 * 34];
    __shared__ __align__(16) float Bs[32 * 98];
    int t = threadIdx.x;
    int r0 = blockIdx.x * 32;
    int tx = t & 15, ty = t >> 4;
    u64 acc[2][3];
    #pragma unroll
    for (int u = 0; u < 2; u++)
        #pragma unroll
        for (int cp = 0; cp < 3; cp++) acc[u][cp] = 0ULL;

    for (int k0 = 0; k0 < DIMC; k0 += 32) {
        __syncthreads();
        {
            int row = t >> 3, c4 = (t & 7) * 4;
            float4 v = *(const float4*)(x + (r0 + row) * DIMC + k0 + c4);
            Ast[(c4 + 0) * 34 + row] = v.x;
            Ast[(c4 + 1) * 34 + row] = v.y;
            Ast[(c4 + 2) * 34 + row] = v.z;
            Ast[(c4 + 3) * 34 + row] = v.w;
        }
        for (int f4 = t; f4 < 768; f4 += 256) {
            int n = f4 >> 3, c4 = (f4 & 7) * 4;
            const float* bp = (n < 32) ? (bq + n * DIMC)
                             : (n < 64) ? (bk + (n - 32) * DIMC)
                                        : (bv + (n - 64) * DIMC);
            float4 v = *(const float4*)(bp + k0 + c4);
            Bs[(c4 + 0) * 98 + n] = v.x;
            Bs[(c4 + 1) * 98 + n] = v.y;
            Bs[(c4 + 2) * 98 + n] = v.z;
            Bs[(c4 + 3) * 98 + n] = v.w;
        }
        __syncthreads();
        #pragma unroll
        for (int kk = 0; kk < 32; kk++) {
            float a0 = Ast[kk * 34 + ty * 2];
            float a1 = Ast[kk * 34 + ty * 2 + 1];
            u64 a02 = pk2(a0, a0), a12 = pk2(a1, a1);
            const u64* bp2 = (const u64*)(Bs + kk * 98 + tx * 6);
            #pragma unroll
            for (int cp = 0; cp < 3; cp++) {
                u64 b2 = bp2[cp];
                acc[0][cp] = fma2(a02, b2, acc[0][cp]);
                acc[1][cp] = fma2(a12, b2, acc[1][cp]);
            }
        }
    }
    #pragma unroll
    for (int u = 0; u < 2; u++)
        #pragma unroll
        for (int cp = 0; cp < 3; cp++) {
            float2 f = upk2(acc[u][cp]);
            int row = r0 + ty * 2 + u;
            int b = row >> 11, l = row & (LSEQ - 1);
            #pragma unroll
            for (int j2 = 0; j2 < 2; j2++) {
                int n = tx * 6 + cp * 2 + j2;
                float val = j2 ? f.y : f.x;
                int p = n >> 5, j = n & 31;
                if (p == 1)
                    g_rkT[(b * HAR + j) * LSEQ + l] = val;
                else
                    g_res[((p * BSZ + b) * LSEQ + l) * HAR + j] = val;
            }
        }
}

// ---------------- K4: flash attention — R10 compute (q4 x k16, full j/g) +
// R13 register-diet staging (unroll-1, loop-carried pointers). 2 CTAs/SM. ----
#define KTBUF (32 * 132)
#define VBUF  (128 * 36)
#define GQPAD 68
__global__ __launch_bounds__(128, 2) void k_attn() {
    extern __shared__ __align__(16) float smem[];
    float* sKT = smem;                        // 2 x KTBUF
    float* sV  = smem + 2 * KTBUF;            // 2 x VBUF
    float* sGq = smem + 2 * KTBUF + 2 * VBUF; // 32 x GQPAD

    int t = threadIdx.x;
    int w = t >> 5, lane = t & 31;
    int qsub = lane >> 3, ksub = lane & 7;
    int q0 = blockIdx.x * 64;
    int bh = blockIdx.y;
    int b = bh >> 4, h = bh & 15;
    const float* rq  = g_res + (0 * BSZ + b) * LSEQ * HAR;
    const float* rv  = g_res + (2 * BSZ + b) * LSEQ * HAR;
    const float* rkT = g_rkT + b * HAR * LSEQ;

    // staging offsets (constants per thread)
    unsigned kbase0 = (unsigned)__cvta_generic_to_shared(sKT);
    unsigned vbase0 = (unsigned)__cvta_generic_to_shared(sV);
    unsigned kdoff = ((t >> 5) * 132 + (t & 31) * 4) * 4;
    int ksoff = (t >> 5) * LSEQ + (t & 31) * 4;
    int p0 = (t & 7) ^ ((t >> 5) & 7);
    unsigned vdoff0 = ((t >> 3) * 36 + p0 * 4) * 4;
    unsigned vdoff1 = ((t >> 3) * 36 + (p0 ^ 4) * 4) * 4 + 2304;
    int vsoff = (t >> 3) * 32 + (t & 7) * 4;

    {   // stage tile 0 into buffer 0
        unsigned kd = kbase0 + kdoff;
        const float* ks = rkT + ksoff;
        #pragma unroll 1
        for (int it = 0; it < 8; it++) { cpa16(kd, ks); kd += 2112; ks += 4 * LSEQ; }
        unsigned vd0 = vbase0 + vdoff0, vd1 = vbase0 + vdoff1;
        const float* vs = rv + vsoff;
        #pragma unroll 1
        for (int it = 0; it < 4; it++) {
            cpa16(vd0, vs); cpa16(vd1, vs + 512);
            vd0 += 4608; vd1 += 4608; vs += 1024;
        }
        cpa_commit();
    }

    {   // phase 0: Gq[64,32] = rq_tile * M, stored transposed sGq[j][64q]
        int q = t >> 1, jbb = (t & 1) * 16;
        const float* rqrow = rq + (q0 + q) * HAR;
        const float* Mrow = g_M + h * 1024;
        float a[16];
        #pragma unroll
        for (int jj = 0; jj < 16; jj++) a[jj] = 0.f;
        #pragma unroll 4
        for (int i = 0; i < 32; i++) {
            float qv = rqrow[i];
            #pragma unroll
            for (int jj = 0; jj < 16; jj++) a[jj] += qv * Mrow[i * 32 + jbb + jj];
        }
        #pragma unroll
        for (int jj = 0; jj < 16; jj++) sGq[(jbb + jj) * GQPAD + q] = a[jj];
    }

    u64 U2[4][16];
    #pragma unroll
    for (int q = 0; q < 4; q++)
        #pragma unroll
        for (int gp = 0; gp < 16; gp++) U2[q][gp] = 0ULL;
    float lac[4];
    #pragma unroll
    for (int q = 0; q < 4; q++) lac[q] = 0.f;
    int qb = w * 16 + qsub * 4;     // lane's first query (block-local)

    for (int kt = 0; kt < 16; kt++) {
        int cb = kt & 1;
        if (kt < 15) {       // stage next tile into the other buffer
            int nb = cb ^ 1;
            unsigned kd = kbase0 + (unsigned)(nb * KTBUF * 4) + kdoff;
            const float* ks = rkT + (kt + 1) * 128 + ksoff;
            #pragma unroll 1
            for (int it = 0; it < 8; it++) { cpa16(kd, ks); kd += 2112; ks += 4 * LSEQ; }
            unsigned vbb = vbase0 + (unsigned)(nb * VBUF * 4);
            unsigned vd0 = vbb + vdoff0, vd1 = vbb + vdoff1;
            const float* vs = rv + (kt + 1) * 128 * HAR + vsoff;
            #pragma unroll 1
            for (int it = 0; it < 4; it++) {
                cpa16(vd0, vs); cpa16(vd1, vs + 512);
                vd0 += 4608; vd1 += 4608; vs += 1024;
            }
            cpa_commit();
            asm volatile("cp.async.wait_group 1;" ::: "memory");
        } else {
            asm volatile("cp.async.wait_group 0;" ::: "memory");
        }
        __syncthreads();

        const float* ktb = sKT + cb * KTBUF;
        const float* vtb = sV + cb * VBUF;

        // ---- S phase: s2[4q][8] pairs over adjacent keys ----
        u64 s2[4][8];
        #pragma unroll
        for (int q = 0; q < 4; q++)
            #pragma unroll
            for (int kp = 0; kp < 8; kp++) s2[q][kp] = 0ULL;
        #pragma unroll 8
        for (int kk = 0; kk < 32; kk++) {
            float4 gqv = *(const float4*)(sGq + kk * GQPAD + qb);  // 4 queries
            u64 a0 = pk2(gqv.x, gqv.x);
            u64 a1 = pk2(gqv.y, gqv.y);
            u64 a2 = pk2(gqv.z, gqv.z);
            u64 a3 = pk2(gqv.w, gqv.w);
            const float* kr = ktb + kk * 132 + ksub * 4;
            #pragma unroll
            for (int tt = 0; tt < 4; tt++) {
                ulonglong2 kv = *(const ulonglong2*)(kr + tt * 32);
                s2[0][tt * 2 + 0] = fma2(a0, kv.x, s2[0][tt * 2 + 0]);
                s2[0][tt * 2 + 1] = fma2(a0, kv.y, s2[0][tt * 2 + 1]);
                s2[1][tt * 2 + 0] = fma2(a1, kv.x, s2[1][tt * 2 + 0]);
                s2[1][tt * 2 + 1] = fma2(a1, kv.y, s2[1][tt * 2 + 1]);
                s2[2][tt * 2 + 0] = fma2(a2, kv.x, s2[2][tt * 2 + 0]);
                s2[2][tt * 2 + 1] = fma2(a2, kv.y, s2[2][tt * 2 + 1]);
                s2[3][tt * 2 + 0] = fma2(a3, kv.x, s2[3][tt * 2 + 0]);
                s2[3][tt * 2 + 1] = fma2(a3, kv.y, s2[3][tt * 2 + 1]);
            }
        }

        // ---- p = exp2(s) directly (logits tiny; no max subtraction needed) ----
        #pragma unroll
        for (int q = 0; q < 4; q++) {
            #pragma unroll
            for (int kp = 0; kp < 8; kp++) {
                float2 f = upk2(s2[q][kp]);
                float px = ex2f(f.x), py = ex2f(f.y);
                s2[q][kp] = pk2(px, py);
                lac[q] += px + py;
            }
        }

        // ---- PV phase: U[4q][32g] += p * V ----
        #pragma unroll
        for (int tt = 0; tt < 4; tt++) {
            #pragma unroll
            for (int jp = 0; jp < 2; jp++) {
                float2 p0v = upk2(s2[0][tt * 2 + jp]);
                float2 p1v = upk2(s2[1][tt * 2 + jp]);
                float2 p2v = upk2(s2[2][tt * 2 + jp]);
                float2 p3v = upk2(s2[3][tt * 2 + jp]);
                #pragma unroll
                for (int j2 = 0; j2 < 2; j2++) {
                    int k = ksub * 4 + tt * 32 + jp * 2 + j2;
                    u64 a0 = j2 ? pk2(p0v.y, p0v.y) : pk2(p0v.x, p0v.x);
                    u64 a1 = j2 ? pk2(p1v.y, p1v.y) : pk2(p1v.x, p1v.x);
                    u64 a2 = j2 ? pk2(p2v.y, p2v.y) : pk2(p2v.x, p2v.x);
                    u64 a3 = j2 ? pk2(p3v.y, p3v.y) : pk2(p3v.x, p3v.x);
                    const float* vr = vtb + k * 36;
                    #pragma unroll
                    for (int gi = 0; gi < 8; gi++) {
                        int pc = gi ^ ksub;
                        ulonglong2 vv = *(const ulonglong2*)(vr + pc * 4);
                        U2[0][2 * gi]     = fma2(a0, vv.x, U2[0][2 * gi]);
                        U2[0][2 * gi + 1] = fma2(a0, vv.y, U2[0][2 * gi + 1]);
                        U2[1][2 * gi]     = fma2(a1, vv.x, U2[1][2 * gi]);
                        U2[1][2 * gi + 1] = fma2(a1, vv.y, U2[1][2 * gi + 1]);
                        U2[2][2 * gi]     = fma2(a2, vv.x, U2[2][2 * gi]);
                        U2[2][2 * gi + 1] = fma2(a2, vv.y, U2[2][2 * gi + 1]);
                        U2[3][2 * gi]     = fma2(a3, vv.x, U2[3][2 * gi]);
                        U2[3][2 * gi + 1] = fma2(a3, vv.y, U2[3][2 * gi + 1]);
                    }
                }
            }
        }
        __syncthreads();
    }

    // ---- final: butterfly-reduce partial U and l over the 8 ksub lanes ----
    #pragma unroll
    for (int d = 1; d <= 4; d <<= 1) {
        #pragma unroll
        for (int q = 0; q < 4; q++) {
            lac[q] += __shfl_xor_sync(0xffffffffu, lac[q], d);
            #pragma unroll
            for (int gp = 0; gp < 16; gp++) {
                u64 o = __shfl_xor_sync(0xffffffffu, U2[q][gp], d);
                U2[q][gp] = add2(U2[q][gp], o);
            }
        }
    }
    #pragma unroll
    for (int q = 0; q < 4; q++) {
        float inv = 1.f / lac[q];
        float* up = g_U + (bh * LSEQ + q0 + qb + q) * HAR + ksub * 4;
        float2 A = upk2(U2[q][ksub * 2]), B2 = upk2(U2[q][ksub * 2 + 1]);
        *(float4*)up = make_float4(A.x * inv, A.y * inv, B2.x * inv, B2.y * inv);
    }
}

// ---------------- K5 (fused mix+out): 16 rows/block ----------------
__global__ __launch_bounds__(256) void k_mixout(float* __restrict__ out) {
    __shared__ __align__(16) float sU[16 * 512];
    __shared__ __align__(16) float sR[16 * 32];
    int t = threadIdx.x;
    int row0 = blockIdx.x * 16;
    int b = row0 >> 11, l0 = row0 & (LSEQ - 1);
    for (int idx = t; idx < 16 * 512; idx += 256) {
        int r = idx >> 9, rest = idx & 511;
        int h = rest >> 5, j = rest & 31;
        sU[idx] = g_U[((b * NH + h) * LSEQ + (l0 + r)) * HAR + j];
    }
    __syncthreads();
    {
        int rp = t >> 5, g = t & 31;
        const float* cp = g_C;
        const float* u0 = sU + (2 * rp) * 512;
        const float* u1 = sU + (2 * rp + 1) * 512;
        u64 acc = 0ULL;
        #pragma unroll 8
        for (int e = 0; e < 512; e++) {
            u64 av = pk2(u0[e], u1[e]);
            float c = cp[e * 32 + g];
            acc = fma2(av, pk2(c, c), acc);
        }
        float2 f = upk2(acc);
        sR[(2 * rp) * 32 + g] = f.x;
        sR[(2 * rp + 1) * 32 + g] = f.y;
    }
    __syncthreads();
    for (int o = t; o < DIMC; o += 256) {
        const u64* wp = (const u64*)(g_wo + o * 32);
        u64 w2[16];
        #pragma unroll
        for (int gp = 0; gp < 16; gp++) w2[gp] = wp[gp];
        #pragma unroll 4
        for (int r = 0; r < 16; r++) {
            const u64* sp = (const u64*)(sR + r * 32);
            u64 acc = 0ULL;
            #pragma unroll
            for (int gp = 0; gp < 16; gp++) acc = fma2(sp[gp], w2[gp], acc);
            float2 f = upk2(acc);
            out[(row0 + r) * DIMC + o] = f.x + f.y;
        }
    }
}

extern "C" void kernel_launch(void* const* d_in, const int* in_sizes, int n_in,
                              void* d_out, int out_size) {
    const float* x   = (const float*)d_in[0];
    const float* bq  = (const float*)d_in[1];
    const float* pq  = (const float*)d_in[2];
    const float* aq  = (const float*)d_in[3];
    const float* bk  = (const float*)d_in[4];
    const float* pk_ = (const float*)d_in[5];
    const float* ak  = (const float*)d_in[6];
    const float* bv  = (const float*)d_in[7];
    const float* pv  = (const float*)d_in[8];
    const float* av  = (const float*)d_in[9];
    const float* bo  = (const float*)d_in[10];
    const float* po  = (const float*)d_in[11];
    const float* ao  = (const float*)d_in[12];
    float* out = (float*)d_out;

    const int attn_smem = (2 * KTBUF + 2 * VBUF + 32 * GQPAD) * (int)sizeof(float);
    cudaFuncSetAttribute(k_attn, cudaFuncAttributeMaxDynamicSharedMemorySize, attn_smem);

    k_mc<<<NH, 1024>>>(aq, pq, ak, pk_, av, pv, bo);
    k_wo<<<32, 1024>>>(ao, po);
    k_res<<<BSZ * LSEQ / 32, 256>>>(x, bq, bk, bv);
    k_attn<<<dim3(LSEQ / 64, BSZ * NH), 128, attn_smem>>>();
    k_mixout<<<BSZ * LSEQ / 16, 256>>>(out);
}